// round 9
// baseline (speedup 1.0000x reference)
#include <cuda_runtime.h>
#include <cstdint>
#include <math.h>

#define BSZ 8
#define SEQ 1024
#define DIM 1024
#define NH 16
#define DH 64
#define MTOK (BSZ*SEQ)        // 8192
#define FFD  (2*DIM)          // 2048
#define QKVD (3*DIM)          // 3072
#define NROW (BSZ*NH*SEQ)     // 131072

// ---------------- scratch (device globals; no runtime allocation) ----------
__device__ float g_qkv[MTOK*QKVD];        // fused q|k|v, row stride 3072
__device__ float g_attn[MTOK*DIM];
__device__ float g_h1[MTOK*DIM];
__device__ float g_ffn[MTOK*FFD];
__device__ float g_xr[MTOK*DIM];          // tf32-rounded x (also reused as scratch)
__device__ float g_wr[8*1024*1024];       // rounded weights: [Wq|Wk|Wv], Wf, W1, W2
__device__ float g_bqkv[QKVD];            // concat bias
__device__ float g_rowsum[NROW];
__device__ float g_rowinv[NROW];

// ================= helpers =================================================
__device__ __forceinline__ uint32_t smem_u32(const void* p) {
    uint32_t a;
    asm("{ .reg .u64 t; cvta.to.shared.u64 t, %1; cvt.u32.u64 %0, t; }"
        : "=r"(a) : "l"(p));
    return a;
}
__device__ __forceinline__ float cvtf(float x) {
    uint32_t u; asm("cvt.rna.tf32.f32 %0, %1;" : "=r"(u) : "f"(x));
    return __uint_as_float(u);
}
#define CP_ASYNC16(s, g) \
    asm volatile("cp.async.cg.shared.global [%0], [%1], 16;" :: "r"(s), "l"(g))
#define CP_COMMIT() asm volatile("cp.async.commit_group;")
#define CP_WAIT1()  asm volatile("cp.async.wait_group 1;")

__device__ __forceinline__ void mma_tf32(float* d, const uint32_t* a, const uint32_t* b) {
    asm volatile(
        "mma.sync.aligned.m16n8k8.row.col.f32.tf32.tf32.f32 "
        "{%0,%1,%2,%3}, {%4,%5,%6,%7}, {%8,%9}, {%0,%1,%2,%3};"
        : "+f"(d[0]), "+f"(d[1]), "+f"(d[2]), "+f"(d[3])
        : "r"(a[0]), "r"(a[1]), "r"(a[2]), "r"(a[3]), "r"(b[0]), "r"(b[1]));
}

// ================= small utility kernels ===================================
__global__ __launch_bounds__(256) void round_copy(
    const float* __restrict__ in, float* __restrict__ out, int n4)
{
    int i = blockIdx.x * blockDim.x + threadIdx.x;
    int stride = gridDim.x * blockDim.x;
    for (; i < n4; i += stride) {
        float4 v = ((const float4*)in)[i];
        v.x = cvtf(v.x); v.y = cvtf(v.y); v.z = cvtf(v.z); v.w = cvtf(v.w);
        ((float4*)out)[i] = v;
    }
}

__global__ __launch_bounds__(256) void zero_buf(float* __restrict__ p, int n)
{
    int i = blockIdx.x * blockDim.x + threadIdx.x;
    if (i < n) p[i] = 0.f;
}

__global__ __launch_bounds__(256) void recip_buf(
    const float* __restrict__ in, float* __restrict__ out, int n)
{
    int i = blockIdx.x * blockDim.x + threadIdx.x;
    if (i < n) out[i] = 1.0f / in[i];
}

__global__ __launch_bounds__(256) void concat_bias(
    const float* __restrict__ a, const float* __restrict__ b,
    const float* __restrict__ c, float* __restrict__ o)
{
    int i = blockIdx.x * blockDim.x + threadIdx.x;
    if (i < DIM) o[i] = a[i];
    else if (i < 2*DIM) o[i] = b[i - DIM];
    else if (i < 3*DIM) o[i] = c[i - 2*DIM];
}

// ================= mma.sync tf32 GEMM ======================================
// MODE 0: plain NT gemm; scale applied to cols < scaleN (after bias).
// MODE 1: per-head scores; epilogue writes e=exp(s) (col SEQ-1 masked to 0)
//         and atomically accumulates row sums into rowsum.
// MODE 2: PV. A = unnormalized e (read), normalized P written back in place,
//         tf32-rounded copy to smem; B = V slice (NN); NT=64.
template <int NT, int MODE>
__global__ __launch_bounds__(256, 2) void gemm_mma(
    const float* __restrict__ A, const float* __restrict__ B,
    const float* __restrict__ bias, const float* __restrict__ res,
    float* __restrict__ C, int K, int lda, int ldb, int ldc,
    float scale, int scaleN, int relu, int roundC,
    float* __restrict__ rowsum, const float* __restrict__ rowinv)
{
    constexpr int ASTR = 36;
    constexpr int BSTR = (MODE == 2) ? 72 : 36;
    constexpr int AFL  = 128 * ASTR;
    constexpr int BFL  = (MODE == 2) ? 32 * BSTR : NT * BSTR;

    constexpr int WROWS = (NT == 128) ? 2 : 4;
    constexpr int WCOLS = 8 / WROWS;
    constexpr int WM = 128 / WROWS;
    constexpr int WN = NT / WCOLS;
    constexpr int MT  = WM / 16;
    constexpr int NTg = WN / 8;

    extern __shared__ char dynsmem[];
    float* const AsB = (float*)dynsmem;
    float* const BsB = AsB + 2 * AFL;

    const int tid = threadIdx.x;
    const int wid = tid >> 5, lane = tid & 31;
    const int g = lane >> 2, t = lane & 3;
    const int wm = (wid % WROWS) * WM;
    const int wn = (wid / WROWS) * WN;

    const int n0 = blockIdx.x * NT;
    const int m0 = blockIdx.y * 128;
    const float* Ap; const float* Bp; float* Cp;
    const float* rinv = nullptr;
    if (MODE == 0) { Ap = A; Bp = B; Cp = C; }
    else if (MODE == 1) {
        const int z = blockIdx.z, b = z >> 4, h = z & 15;
        Ap = A + (size_t)b * SEQ * lda + h * DH;
        Bp = B + (size_t)b * SEQ * ldb + h * DH;
        Cp = C + (size_t)z * SEQ * SEQ;
    } else {
        const int z = blockIdx.z, b = z >> 4, h = z & 15;
        Ap = A + (size_t)z * SEQ * SEQ;          // e rows for this (b,h)
        Bp = B + (size_t)b * SEQ * ldb + h * DH; // V slice
        Cp = C + (size_t)b * SEQ * ldc + h * DH;
        rinv = rowinv + (size_t)z * SEQ;
    }

    float acc[MT][NTg][4];
#pragma unroll
    for (int i = 0; i < MT; i++)
#pragma unroll
        for (int j = 0; j < NTg; j++)
#pragma unroll
            for (int q = 0; q < 4; q++) acc[i][j][q] = 0.f;

    const int Kc = K >> 5;

    auto load_slab_ab = [&](int c, int buf) {
        const int kt = c << 5;
        float* As = AsB + buf * AFL;
        float* Bs = BsB + buf * BFL;
#pragma unroll
        for (int i = 0; i < 4; i++) {
            const int lin = i * 256 + tid;
            const int row = lin >> 3, c16 = lin & 7;
            CP_ASYNC16(smem_u32(As + row * ASTR + c16 * 4),
                       Ap + (size_t)(m0 + row) * lda + kt + c16 * 4);
        }
#pragma unroll
        for (int i = 0; i < NT / 32; i++) {
            const int lin = i * 256 + tid;
            const int row = lin >> 3, c16 = lin & 7;
            CP_ASYNC16(smem_u32(Bs + row * BSTR + c16 * 4),
                       Bp + (size_t)(n0 + row) * ldb + kt + c16 * 4);
        }
    };
    auto load_slab_b2 = [&](int c, int buf) {   // MODE 2: V slab 32x64
        const int kt = c << 5;
        float* Bs = BsB + buf * BFL;
#pragma unroll
        for (int i = 0; i < 2; i++) {
            const int lin = i * 256 + tid;
            const int krow = lin >> 4, c16 = lin & 15;
            CP_ASYNC16(smem_u32(Bs + krow * BSTR + c16 * 4),
                       Bp + (size_t)(kt + krow) * ldb + c16 * 4);
        }
    };

    if (MODE != 2) { load_slab_ab(0, 0); }
    else           { load_slab_b2(0, 0); }
    CP_COMMIT();

    for (int c = 0; c < Kc; c++) {
        if (MODE != 2) {
            if (c + 1 < Kc) load_slab_ab(c + 1, (c + 1) & 1);
            CP_COMMIT();
        } else {
            if (c + 1 < Kc) load_slab_b2(c + 1, (c + 1) & 1);
            CP_COMMIT();
            // A slab: read e, normalize, write P back, rounded copy to smem
            const int kt = c << 5;
            float* Amut = const_cast<float*>(Ap);
#pragma unroll
            for (int i = 0; i < 4; i++) {
                const int lin = i * 256 + tid;
                const int row = lin >> 3, c16 = lin & 7;
                float* gp = Amut + (size_t)(m0 + row) * lda + kt + c16 * 4;
                float4 e4 = *(const float4*)gp;
                const float iv = rinv[m0 + row];
                e4.x *= iv; e4.y *= iv; e4.z *= iv; e4.w *= iv;
                *(float4*)gp = e4;
                float* sd = AsB + row * ASTR + c16 * 4;
                sd[0] = cvtf(e4.x); sd[1] = cvtf(e4.y);
                sd[2] = cvtf(e4.z); sd[3] = cvtf(e4.w);
            }
        }
        CP_WAIT1();
        __syncthreads();

        const float* As = (MODE == 2) ? AsB : (AsB + (c & 1) * AFL);
        const float* Bs = BsB + (c & 1) * BFL;
#pragma unroll
        for (int ks = 0; ks < 4; ks++) {
            const int kk = ks * 8;
            uint32_t af[MT][4];
#pragma unroll
            for (int mt = 0; mt < MT; mt++) {
                const float* ar = As + (wm + mt * 16 + g) * ASTR + kk + t;
                af[mt][0] = __float_as_uint(ar[0]);
                af[mt][1] = __float_as_uint(ar[8 * ASTR]);
                af[mt][2] = __float_as_uint(ar[4]);
                af[mt][3] = __float_as_uint(ar[8 * ASTR + 4]);
            }
            uint32_t bf[NTg][2];
#pragma unroll
            for (int nt = 0; nt < NTg; nt++) {
                if (MODE != 2) {
                    const float* br = Bs + (wn + nt * 8 + g) * BSTR + kk + t;
                    bf[nt][0] = __float_as_uint(br[0]);
                    bf[nt][1] = __float_as_uint(br[4]);
                } else {
                    const float* br = Bs + (kk + t) * BSTR + wn + nt * 8 + g;
                    bf[nt][0] = __float_as_uint(br[0]);
                    bf[nt][1] = __float_as_uint(br[4 * BSTR]);
                }
            }
#pragma unroll
            for (int mt = 0; mt < MT; mt++)
#pragma unroll
                for (int nt = 0; nt < NTg; nt++)
                    mma_tf32(acc[mt][nt], af[mt], bf[nt]);
        }
        __syncthreads();
    }

    // ---- epilogue ----
    if (MODE == 1) {
        float rpart[MT][2];
#pragma unroll
        for (int mt = 0; mt < MT; mt++) { rpart[mt][0] = 0.f; rpart[mt][1] = 0.f; }
#pragma unroll
        for (int mt = 0; mt < MT; mt++) {
            const int row = m0 + wm + mt * 16 + g;
#pragma unroll
            for (int nt = 0; nt < NTg; nt++) {
                const int col = n0 + wn + nt * 8 + 2 * t;
                float e0 = __expf(acc[mt][nt][0]);
                float e1 = __expf(acc[mt][nt][1]);
                float e2 = __expf(acc[mt][nt][2]);
                float e3 = __expf(acc[mt][nt][3]);
                if (col == SEQ - 1)     { e0 = 0.f; e2 = 0.f; }
                if (col + 1 == SEQ - 1) { e1 = 0.f; e3 = 0.f; }
                *(float2*)&Cp[(size_t)row * ldc + col]       = make_float2(e0, e1);
                *(float2*)&Cp[(size_t)(row + 8) * ldc + col] = make_float2(e2, e3);
                rpart[mt][0] += e0 + e1;
                rpart[mt][1] += e2 + e3;
            }
        }
#pragma unroll
        for (int mt = 0; mt < MT; mt++) {
#pragma unroll
            for (int s = 0; s < 2; s++) {
                rpart[mt][s] += __shfl_xor_sync(0xffffffffu, rpart[mt][s], 1);
                rpart[mt][s] += __shfl_xor_sync(0xffffffffu, rpart[mt][s], 2);
            }
        }
        if (t == 0) {
            float* rs = rowsum + (size_t)blockIdx.z * SEQ + m0;
#pragma unroll
            for (int mt = 0; mt < MT; mt++) {
                atomicAdd(&rs[wm + mt * 16 + g],     rpart[mt][0]);
                atomicAdd(&rs[wm + mt * 16 + g + 8], rpart[mt][1]);
            }
        }
        return;
    }

#pragma unroll
    for (int mt = 0; mt < MT; mt++) {
        const int row = m0 + wm + mt * 16 + g;
#pragma unroll
        for (int nt = 0; nt < NTg; nt++) {
            const int col = n0 + wn + nt * 8 + 2 * t;
            float o0 = acc[mt][nt][0], o1 = acc[mt][nt][1];
            float o2 = acc[mt][nt][2], o3 = acc[mt][nt][3];
            if (bias) {
                const float b0 = bias[col], b1 = bias[col + 1];
                o0 += b0; o1 += b1; o2 += b0; o3 += b1;
            }
            if (scale != 1.f && col < scaleN) {
                o0 *= scale; o1 *= scale; o2 *= scale; o3 *= scale;
            }
            if (res) {
                float2 r0 = *(const float2*)&res[(size_t)row * ldc + col];
                float2 r1 = *(const float2*)&res[(size_t)(row + 8) * ldc + col];
                o0 += r0.x; o1 += r0.y; o2 += r1.x; o3 += r1.y;
            }
            if (relu) {
                o0 = fmaxf(o0, 0.f); o1 = fmaxf(o1, 0.f);
                o2 = fmaxf(o2, 0.f); o3 = fmaxf(o3, 0.f);
            }
            if (roundC) {
                o0 = cvtf(o0); o1 = cvtf(o1); o2 = cvtf(o2); o3 = cvtf(o3);
            }
            *(float2*)&Cp[(size_t)row * ldc + col]       = make_float2(o0, o1);
            *(float2*)&Cp[(size_t)(row + 8) * ldc + col] = make_float2(o2, o3);
        }
    }
}

// ================= layernorm ==============================================
__global__ __launch_bounds__(256) void layernorm_row(
    const float* __restrict__ in, float* __restrict__ out,
    const float* __restrict__ g, const float* __restrict__ be, int roundC)
{
    __shared__ float sm[8], sq[8];
    const size_t base = (size_t)blockIdx.x * DIM;
    const int tid = threadIdx.x;
    const int lane = tid & 31, wid = tid >> 5;

    float4 v = *(const float4*)&in[base + tid*4];
    float s  = v.x + v.y + v.z + v.w;
    float s2 = v.x*v.x + v.y*v.y + v.z*v.z + v.w*v.w;
#pragma unroll
    for (int o = 16; o; o >>= 1) {
        s  += __shfl_xor_sync(0xffffffffu, s,  o);
        s2 += __shfl_xor_sync(0xffffffffu, s2, o);
    }
    if (lane == 0) { sm[wid] = s; sq[wid] = s2; }
    __syncthreads();
    if (tid == 0) {
        float tt = 0.f, t2 = 0.f;
#pragma unroll
        for (int i = 0; i < 8; i++) { tt += sm[i]; t2 += sq[i]; }
        sm[0] = tt; sq[0] = t2;
    }
    __syncthreads();
    const float mean = sm[0] * (1.f / DIM);
    const float var  = sq[0] * (1.f / DIM) - mean * mean;
    const float r = rsqrtf(var + 1e-5f);

    float4 gg = *(const float4*)&g[tid*4];
    float4 bb = *(const float4*)&be[tid*4];
    float4 o4;
    o4.x = (v.x - mean) * r * gg.x + bb.x;
    o4.y = (v.y - mean) * r * gg.y + bb.y;
    o4.z = (v.z - mean) * r * gg.z + bb.z;
    o4.w = (v.w - mean) * r * gg.w + bb.w;
    if (roundC) {
        o4.x = cvtf(o4.x); o4.y = cvtf(o4.y);
        o4.z = cvtf(o4.z); o4.w = cvtf(o4.w);
    }
    *(float4*)&out[base + tid*4] = o4;
}

// ================= launcher ================================================
static const int SMEM_GEMM = 2 * (128*36 + 128*36) * 4;      // 73728
static const int SMEM_PV   = (2 * 128*36 + 2 * 32*72) * 4;   // 55296

extern "C" void kernel_launch(void* const* d_in, const int* in_sizes, int n_in,
                              void* d_out, int out_size)
{
    const float* x  = (const float*)d_in[0];
    const float* Wq = (const float*)d_in[1];
    const float* bq = (const float*)d_in[2];
    const float* Wk = (const float*)d_in[3];
    const float* bk = (const float*)d_in[4];
    const float* Wv = (const float*)d_in[5];
    const float* bv = (const float*)d_in[6];
    const float* Wf = (const float*)d_in[7];
    const float* bf = (const float*)d_in[8];
    const float* W1 = (const float*)d_in[9];
    const float* b1 = (const float*)d_in[10];
    const float* W2 = (const float*)d_in[11];
    const float* b2 = (const float*)d_in[12];
    const float* g1 = (const float*)d_in[13];
    const float* be1= (const float*)d_in[14];
    const float* g2 = (const float*)d_in[15];
    const float* be2= (const float*)d_in[16];

    float* out   = (float*)d_out;
    float* score = out + (size_t)MTOK * DIM;

    float *pqkv, *pattn, *ph1, *pffn, *pxr, *pwr, *pbias, *prsum, *prinv;
    cudaGetSymbolAddress((void**)&pqkv,  g_qkv);
    cudaGetSymbolAddress((void**)&pattn, g_attn);
    cudaGetSymbolAddress((void**)&ph1,   g_h1);
    cudaGetSymbolAddress((void**)&pffn,  g_ffn);
    cudaGetSymbolAddress((void**)&pxr,   g_xr);
    cudaGetSymbolAddress((void**)&pwr,   g_wr);
    cudaGetSymbolAddress((void**)&pbias, g_bqkv);
    cudaGetSymbolAddress((void**)&prsum, g_rowsum);
    cudaGetSymbolAddress((void**)&prinv, g_rowinv);

    float* rWqkv = pwr;                    // 3M floats: Wq|Wk|Wv
    float* rWf   = pwr + 3*1024*1024;
    float* rW1   = pwr + 4*1024*1024;
    float* rW2   = pwr + 6*1024*1024;

    cudaFuncSetAttribute(gemm_mma<128,0>, cudaFuncAttributeMaxDynamicSharedMemorySize, SMEM_GEMM);
    cudaFuncSetAttribute(gemm_mma<128,1>, cudaFuncAttributeMaxDynamicSharedMemorySize, SMEM_GEMM);
    cudaFuncSetAttribute(gemm_mma<64,2>,  cudaFuncAttributeMaxDynamicSharedMemorySize, SMEM_PV);

    const float isq = 0.125f;  // 1/sqrt(64)

    // ---- prep: rounding, bias concat, rowsum zero ----
    round_copy<<<2048, 256>>>(x,  pxr, MTOK*DIM/4);
    round_copy<<<1024, 256>>>(Wq, rWqkv,               DIM*DIM/4);
    round_copy<<<1024, 256>>>(Wk, rWqkv + 1024*1024,   DIM*DIM/4);
    round_copy<<<1024, 256>>>(Wv, rWqkv + 2*1024*1024, DIM*DIM/4);
    round_copy<<<1024, 256>>>(Wf, rWf, DIM*DIM/4);
    round_copy<<<2048, 256>>>(W1, rW1, FFD*DIM/4);
    round_copy<<<2048, 256>>>(W2, rW2, FFD*DIM/4);
    concat_bias<<<12, 256>>>(bq, bk, bv, pbias);
    zero_buf<<<NROW/256, 256>>>(prsum, NROW);

    // ---- fused QKV projection (q cols scaled by 1/sqrt(dh); all rounded) ----
    gemm_mma<128,0><<<dim3(QKVD/128, MTOK/128), 256, SMEM_GEMM>>>(
        pxr, rWqkv, pbias, nullptr, pqkv, DIM, DIM, DIM, QKVD,
        isq, DIM, 0, 1, nullptr, nullptr);

    // ---- scores: e = exp(q.k^T) -> score region; rowsums accumulated ----
    gemm_mma<128,1><<<dim3(SEQ/128, SEQ/128, BSZ*NH), 256, SMEM_GEMM>>>(
        pqkv, pqkv + DIM, nullptr, nullptr, score, DH, QKVD, QKVD, SEQ,
        1.f, 0, 0, 0, prsum, nullptr);
    recip_buf<<<NROW/256, 256>>>(prsum, prinv, NROW);

    // ---- PV: normalize e in place (final P to d_out), attn = P @ V ----
    gemm_mma<64,2><<<dim3(1, SEQ/128, BSZ*NH), 256, SMEM_PV>>>(
        score, pqkv + 2*DIM, nullptr, nullptr, pattn, SEQ, SEQ, QKVD, DIM,
        1.f, 0, 0, 1, nullptr, prinv);

    // ---- output projection + residual, LN1 ----
    gemm_mma<128,0><<<dim3(DIM/128, MTOK/128), 256, SMEM_GEMM>>>(
        pattn, rWf, bf, x, ph1, DIM, DIM, DIM, DIM,
        1.f, 0, 0, 0, nullptr, nullptr);
    layernorm_row<<<MTOK, 256>>>(ph1, ph1, g1, be1, 1);

    // ---- FFN ----
    gemm_mma<128,0><<<dim3(FFD/128, MTOK/128), 256, SMEM_GEMM>>>(
        ph1, rW1, b1, nullptr, pffn, DIM, DIM, DIM, FFD,
        1.f, 0, 1, 1, nullptr, nullptr);
    gemm_mma<128,0><<<dim3(DIM/128, MTOK/128), 256, SMEM_GEMM>>>(
        pffn, rW2, b2, ph1, pxr, FFD, FFD, FFD, DIM,
        1.f, 0, 0, 0, nullptr, nullptr);
    layernorm_row<<<MTOK, 256>>>(pxr, out, g2, be2, 0);
}

// round 10
// speedup vs baseline: 1.2106x; 1.2106x over previous
#include <cuda_runtime.h>
#include <cstdint>
#include <math.h>

#define BSZ 8
#define SEQ 1024
#define DIM 1024
#define NH 16
#define DH 64
#define MTOK (BSZ*SEQ)        // 8192
#define FFD  (2*DIM)          // 2048
#define QKVD (3*DIM)          // 3072
#define NROW (BSZ*NH*SEQ)     // 131072

// ---------------- scratch (device globals; no runtime allocation) ----------
__device__ float g_qkv[MTOK*QKVD];        // fused q|k|v, row stride 3072
__device__ float g_attn[MTOK*DIM];
__device__ float g_h1[MTOK*DIM];
__device__ float g_ffn[MTOK*FFD];
__device__ float g_xr[MTOK*DIM];          // tf32-rounded x / late scratch
__device__ float g_wr[8*1024*1024];       // rounded weights: [Wq|Wk|Wv], Wf, W1, W2
__device__ float g_bqkv[QKVD];            // concat bias
__device__ float g_rowsum[NROW];
__device__ float g_rowinv[NROW];

// ================= helpers =================================================
__device__ __forceinline__ uint32_t smem_u32(const void* p) {
    uint32_t a;
    asm("{ .reg .u64 t; cvta.to.shared.u64 t, %1; cvt.u32.u64 %0, t; }"
        : "=r"(a) : "l"(p));
    return a;
}
__device__ __forceinline__ float cvtf(float x) {
    uint32_t u; asm("cvt.rna.tf32.f32 %0, %1;" : "=r"(u) : "f"(x));
    return __uint_as_float(u);
}
#define CP_ASYNC16(s, g) \
    asm volatile("cp.async.cg.shared.global [%0], [%1], 16;" :: "r"(s), "l"(g))
#define CP_COMMIT() asm volatile("cp.async.commit_group;")
#define CP_WAIT1()  asm volatile("cp.async.wait_group 1;")

__device__ __forceinline__ void mma_tf32(float* d, const uint32_t* a, const uint32_t* b) {
    asm volatile(
        "mma.sync.aligned.m16n8k8.row.col.f32.tf32.tf32.f32 "
        "{%0,%1,%2,%3}, {%4,%5,%6,%7}, {%8,%9}, {%0,%1,%2,%3};"
        : "+f"(d[0]), "+f"(d[1]), "+f"(d[2]), "+f"(d[3])
        : "r"(a[0]), "r"(a[1]), "r"(a[2]), "r"(a[3]), "r"(b[0]), "r"(b[1]));
}

// ================= small utility kernels ===================================
struct RC7 {
    const float* in[7];
    float* out[7];
    int n4[7];
};
__global__ __launch_bounds__(256) void round_multi(RC7 rc)
{
    const int j = blockIdx.y;
    const float* __restrict__ in = rc.in[j];
    float* __restrict__ out = rc.out[j];
    const int n4 = rc.n4[j];
    int i = blockIdx.x * blockDim.x + threadIdx.x;
    const int stride = gridDim.x * blockDim.x;
    for (; i < n4; i += stride) {
        float4 v = ((const float4*)in)[i];
        v.x = cvtf(v.x); v.y = cvtf(v.y); v.z = cvtf(v.z); v.w = cvtf(v.w);
        ((float4*)out)[i] = v;
    }
}

__global__ __launch_bounds__(256) void zero_buf(float* __restrict__ p, int n)
{
    int i = blockIdx.x * blockDim.x + threadIdx.x;
    if (i < n) p[i] = 0.f;
}

__global__ __launch_bounds__(256) void recip_buf(
    const float* __restrict__ in, float* __restrict__ out, int n)
{
    int i = blockIdx.x * blockDim.x + threadIdx.x;
    if (i < n) out[i] = 1.0f / in[i];
}

__global__ __launch_bounds__(256) void concat_bias(
    const float* __restrict__ a, const float* __restrict__ b,
    const float* __restrict__ c, float* __restrict__ o)
{
    int i = blockIdx.x * blockDim.x + threadIdx.x;
    if (i < DIM) o[i] = a[i];
    else if (i < 2*DIM) o[i] = b[i - DIM];
    else if (i < 3*DIM) o[i] = c[i - 2*DIM];
}

// ================= mma.sync tf32 GEMM ======================================
// MODE 0: plain NT gemm; scale applied to cols < scaleN (after bias).
// MODE 1: per-head scores; epilogue writes e=exp(s) (col SEQ-1 -> 0) and
//         atomically accumulates row sums.
// MODE 2: PV. A = unnormalized e via cp.async (double-buffered); fragments
//         normalized by rowinv (+RNA round); normalized fp32 P written to A
//         in place from smem; B = V slice (NN); NT=64.
template <int NT, int MODE>
__global__ __launch_bounds__(256, 2) void gemm_mma(
    const float* __restrict__ A, const float* __restrict__ B,
    const float* __restrict__ bias, const float* __restrict__ res,
    float* __restrict__ C, int K, int lda, int ldb, int ldc,
    float scale, int scaleN, int relu, int roundC,
    float* __restrict__ rowsum, const float* __restrict__ rowinv)
{
    constexpr int ASTR = 36;
    constexpr int BSTR = (MODE == 2) ? 72 : 36;
    constexpr int AFL  = 128 * ASTR;
    constexpr int BFL  = (MODE == 2) ? 32 * BSTR : NT * BSTR;

    constexpr int WROWS = (NT == 128) ? 2 : 4;
    constexpr int WCOLS = 8 / WROWS;
    constexpr int WM = 128 / WROWS;
    constexpr int WN = NT / WCOLS;
    constexpr int MT  = WM / 16;
    constexpr int NTg = WN / 8;

    extern __shared__ char dynsmem[];
    float* const AsB = (float*)dynsmem;
    float* const BsB = AsB + 2 * AFL;

    const int tid = threadIdx.x;
    const int wid = tid >> 5, lane = tid & 31;
    const int g = lane >> 2, t = lane & 3;
    const int wm = (wid % WROWS) * WM;
    const int wn = (wid / WROWS) * WN;

    const int n0 = blockIdx.x * NT;
    const int m0 = blockIdx.y * 128;
    const float* Ap; const float* Bp; float* Cp;
    if (MODE == 0) { Ap = A; Bp = B; Cp = C; }
    else if (MODE == 1) {
        const int z = blockIdx.z, b = z >> 4, h = z & 15;
        Ap = A + (size_t)b * SEQ * lda + h * DH;
        Bp = B + (size_t)b * SEQ * ldb + h * DH;
        Cp = C + (size_t)z * SEQ * SEQ;
    } else {
        const int z = blockIdx.z, b = z >> 4, h = z & 15;
        Ap = A + (size_t)z * SEQ * SEQ;          // e rows for this (b,h)
        Bp = B + (size_t)b * SEQ * ldb + h * DH; // V slice
        Cp = C + (size_t)b * SEQ * ldc + h * DH;
    }

    // MODE 2: per-thread fixed row-normalizers
    float rvf[4] = {1.f, 1.f, 1.f, 1.f};   // fragment rows
    float rvw[4] = {1.f, 1.f, 1.f, 1.f};   // P-write rows
    if (MODE == 2) {
        const float* rinv = rowinv + (size_t)blockIdx.z * SEQ + m0;
#pragma unroll
        for (int mt = 0; mt < MT; mt++) {
            rvf[2*mt]   = rinv[wm + mt * 16 + g];
            rvf[2*mt+1] = rinv[wm + mt * 16 + g + 8];
        }
#pragma unroll
        for (int i = 0; i < 4; i++)
            rvw[i] = rinv[(i * 256 + tid) >> 3];
    }

    float acc[MT][NTg][4];
#pragma unroll
    for (int i = 0; i < MT; i++)
#pragma unroll
        for (int j = 0; j < NTg; j++)
#pragma unroll
            for (int q = 0; q < 4; q++) acc[i][j][q] = 0.f;

    const int Kc = K >> 5;

    auto load_slab_a = [&](int c, int buf) {
        const int kt = c << 5;
        float* As = AsB + buf * AFL;
#pragma unroll
        for (int i = 0; i < 4; i++) {
            const int lin = i * 256 + tid;
            const int row = lin >> 3, c16 = lin & 7;
            CP_ASYNC16(smem_u32(As + row * ASTR + c16 * 4),
                       Ap + (size_t)(m0 + row) * lda + kt + c16 * 4);
        }
    };
    auto load_slab_b = [&](int c, int buf) {
        const int kt = c << 5;
        float* Bs = BsB + buf * BFL;
        if (MODE != 2) {
#pragma unroll
            for (int i = 0; i < NT / 32; i++) {
                const int lin = i * 256 + tid;
                const int row = lin >> 3, c16 = lin & 7;
                CP_ASYNC16(smem_u32(Bs + row * BSTR + c16 * 4),
                           Bp + (size_t)(n0 + row) * ldb + kt + c16 * 4);
            }
        } else {
#pragma unroll
            for (int i = 0; i < 2; i++) {
                const int lin = i * 256 + tid;
                const int krow = lin >> 4, c16 = lin & 15;
                CP_ASYNC16(smem_u32(Bs + krow * BSTR + c16 * 4),
                           Bp + (size_t)(kt + krow) * ldb + c16 * 4);
            }
        }
    };

    load_slab_a(0, 0);
    load_slab_b(0, 0);
    CP_COMMIT();

    for (int c = 0; c < Kc; c++) {
        if (c + 1 < Kc) {
            load_slab_a(c + 1, (c + 1) & 1);
            load_slab_b(c + 1, (c + 1) & 1);
        }
        CP_COMMIT();
        CP_WAIT1();
        __syncthreads();

        const float* As = AsB + (c & 1) * AFL;
        const float* Bs = BsB + (c & 1) * BFL;
#pragma unroll
        for (int ks = 0; ks < 4; ks++) {
            const int kk = ks * 8;
            uint32_t af[MT][4];
#pragma unroll
            for (int mt = 0; mt < MT; mt++) {
                const float* ar = As + (wm + mt * 16 + g) * ASTR + kk + t;
                if (MODE == 2) {
                    af[mt][0] = __float_as_uint(cvtf(ar[0]            * rvf[2*mt]));
                    af[mt][1] = __float_as_uint(cvtf(ar[8 * ASTR]     * rvf[2*mt+1]));
                    af[mt][2] = __float_as_uint(cvtf(ar[4]            * rvf[2*mt]));
                    af[mt][3] = __float_as_uint(cvtf(ar[8 * ASTR + 4] * rvf[2*mt+1]));
                } else {
                    af[mt][0] = __float_as_uint(ar[0]);
                    af[mt][1] = __float_as_uint(ar[8 * ASTR]);
                    af[mt][2] = __float_as_uint(ar[4]);
                    af[mt][3] = __float_as_uint(ar[8 * ASTR + 4]);
                }
            }
            uint32_t bf[NTg][2];
#pragma unroll
            for (int nt = 0; nt < NTg; nt++) {
                if (MODE != 2) {
                    const float* br = Bs + (wn + nt * 8 + g) * BSTR + kk + t;
                    bf[nt][0] = __float_as_uint(br[0]);
                    bf[nt][1] = __float_as_uint(br[4]);
                } else {
                    const float* br = Bs + (kk + t) * BSTR + wn + nt * 8 + g;
                    bf[nt][0] = __float_as_uint(br[0]);
                    bf[nt][1] = __float_as_uint(br[4 * BSTR]);
                }
            }
#pragma unroll
            for (int mt = 0; mt < MT; mt++)
#pragma unroll
                for (int nt = 0; nt < NTg; nt++)
                    mma_tf32(acc[mt][nt], af[mt], bf[nt]);
        }

        if (MODE == 2) {
            // write normalized fp32 P back to gmem from the smem slab
            const int kt = c << 5;
            float* Amut = const_cast<float*>(Ap);
#pragma unroll
            for (int i = 0; i < 4; i++) {
                const int lin = i * 256 + tid;
                const int row = lin >> 3, c16 = lin & 7;
                float4 e4 = *(const float4*)(As + row * ASTR + c16 * 4);
                const float iv = rvw[i];
                e4.x *= iv; e4.y *= iv; e4.z *= iv; e4.w *= iv;
                *(float4*)(Amut + (size_t)(m0 + row) * lda + kt + c16 * 4) = e4;
            }
        }
        __syncthreads();
    }

    // ---- epilogue ----
    if (MODE == 1) {
        float rpart[MT][2];
#pragma unroll
        for (int mt = 0; mt < MT; mt++) { rpart[mt][0] = 0.f; rpart[mt][1] = 0.f; }
#pragma unroll
        for (int mt = 0; mt < MT; mt++) {
            const int row = m0 + wm + mt * 16 + g;
#pragma unroll
            for (int nt = 0; nt < NTg; nt++) {
                const int col = n0 + wn + nt * 8 + 2 * t;
                float e0 = __expf(acc[mt][nt][0]);
                float e1 = __expf(acc[mt][nt][1]);
                float e2 = __expf(acc[mt][nt][2]);
                float e3 = __expf(acc[mt][nt][3]);
                if (col == SEQ - 1)     { e0 = 0.f; e2 = 0.f; }
                if (col + 1 == SEQ - 1) { e1 = 0.f; e3 = 0.f; }
                *(float2*)&Cp[(size_t)row * ldc + col]       = make_float2(e0, e1);
                *(float2*)&Cp[(size_t)(row + 8) * ldc + col] = make_float2(e2, e3);
                rpart[mt][0] += e0 + e1;
                rpart[mt][1] += e2 + e3;
            }
        }
#pragma unroll
        for (int mt = 0; mt < MT; mt++) {
#pragma unroll
            for (int s = 0; s < 2; s++) {
                rpart[mt][s] += __shfl_xor_sync(0xffffffffu, rpart[mt][s], 1);
                rpart[mt][s] += __shfl_xor_sync(0xffffffffu, rpart[mt][s], 2);
            }
        }
        if (t == 0) {
            float* rs = rowsum + (size_t)blockIdx.z * SEQ + m0;
#pragma unroll
            for (int mt = 0; mt < MT; mt++) {
                atomicAdd(&rs[wm + mt * 16 + g],     rpart[mt][0]);
                atomicAdd(&rs[wm + mt * 16 + g + 8], rpart[mt][1]);
            }
        }
        return;
    }

#pragma unroll
    for (int mt = 0; mt < MT; mt++) {
        const int row = m0 + wm + mt * 16 + g;
#pragma unroll
        for (int nt = 0; nt < NTg; nt++) {
            const int col = n0 + wn + nt * 8 + 2 * t;
            float o0 = acc[mt][nt][0], o1 = acc[mt][nt][1];
            float o2 = acc[mt][nt][2], o3 = acc[mt][nt][3];
            if (bias) {
                const float b0 = bias[col], b1 = bias[col + 1];
                o0 += b0; o1 += b1; o2 += b0; o3 += b1;
            }
            if (scale != 1.f && col < scaleN) {
                o0 *= scale; o1 *= scale; o2 *= scale; o3 *= scale;
            }
            if (res) {
                float2 r0 = *(const float2*)&res[(size_t)row * ldc + col];
                float2 r1 = *(const float2*)&res[(size_t)(row + 8) * ldc + col];
                o0 += r0.x; o1 += r0.y; o2 += r1.x; o3 += r1.y;
            }
            if (relu) {
                o0 = fmaxf(o0, 0.f); o1 = fmaxf(o1, 0.f);
                o2 = fmaxf(o2, 0.f); o3 = fmaxf(o3, 0.f);
            }
            if (roundC) {
                o0 = cvtf(o0); o1 = cvtf(o1); o2 = cvtf(o2); o3 = cvtf(o3);
            }
            *(float2*)&Cp[(size_t)row * ldc + col]       = make_float2(o0, o1);
            *(float2*)&Cp[(size_t)(row + 8) * ldc + col] = make_float2(o2, o3);
        }
    }
}

// ================= layernorm ==============================================
__global__ __launch_bounds__(256) void layernorm_row(
    const float* __restrict__ in, float* __restrict__ out,
    const float* __restrict__ g, const float* __restrict__ be, int roundC)
{
    __shared__ float sm[8], sq[8];
    const size_t base = (size_t)blockIdx.x * DIM;
    const int tid = threadIdx.x;
    const int lane = tid & 31, wid = tid >> 5;

    float4 v = *(const float4*)&in[base + tid*4];
    float s  = v.x + v.y + v.z + v.w;
    float s2 = v.x*v.x + v.y*v.y + v.z*v.z + v.w*v.w;
#pragma unroll
    for (int o = 16; o; o >>= 1) {
        s  += __shfl_xor_sync(0xffffffffu, s,  o);
        s2 += __shfl_xor_sync(0xffffffffu, s2, o);
    }
    if (lane == 0) { sm[wid] = s; sq[wid] = s2; }
    __syncthreads();
    if (tid == 0) {
        float tt = 0.f, t2 = 0.f;
#pragma unroll
        for (int i = 0; i < 8; i++) { tt += sm[i]; t2 += sq[i]; }
        sm[0] = tt; sq[0] = t2;
    }
    __syncthreads();
    const float mean = sm[0] * (1.f / DIM);
    const float var  = sq[0] * (1.f / DIM) - mean * mean;
    const float r = rsqrtf(var + 1e-5f);

    float4 gg = *(const float4*)&g[tid*4];
    float4 bb = *(const float4*)&be[tid*4];
    float4 o4;
    o4.x = (v.x - mean) * r * gg.x + bb.x;
    o4.y = (v.y - mean) * r * gg.y + bb.y;
    o4.z = (v.z - mean) * r * gg.z + bb.z;
    o4.w = (v.w - mean) * r * gg.w + bb.w;
    if (roundC) {
        o4.x = cvtf(o4.x); o4.y = cvtf(o4.y);
        o4.z = cvtf(o4.z); o4.w = cvtf(o4.w);
    }
    *(float4*)&out[base + tid*4] = o4;
}

// ================= launcher ================================================
static const int SMEM_GEMM = 2 * (128*36 + 128*36) * 4;      // 73728
static const int SMEM_PV   = (2 * 128*36 + 2 * 32*72) * 4;   // 55296

extern "C" void kernel_launch(void* const* d_in, const int* in_sizes, int n_in,
                              void* d_out, int out_size)
{
    const float* x  = (const float*)d_in[0];
    const float* Wq = (const float*)d_in[1];
    const float* bq = (const float*)d_in[2];
    const float* Wk = (const float*)d_in[3];
    const float* bk = (const float*)d_in[4];
    const float* Wv = (const float*)d_in[5];
    const float* bv = (const float*)d_in[6];
    const float* Wf = (const float*)d_in[7];
    const float* bf = (const float*)d_in[8];
    const float* W1 = (const float*)d_in[9];
    const float* b1 = (const float*)d_in[10];
    const float* W2 = (const float*)d_in[11];
    const float* b2 = (const float*)d_in[12];
    const float* g1 = (const float*)d_in[13];
    const float* be1= (const float*)d_in[14];
    const float* g2 = (const float*)d_in[15];
    const float* be2= (const float*)d_in[16];

    float* out   = (float*)d_out;
    float* score = out + (size_t)MTOK * DIM;

    float *pqkv, *pattn, *ph1, *pffn, *pxr, *pwr, *pbias, *prsum, *prinv;
    cudaGetSymbolAddress((void**)&pqkv,  g_qkv);
    cudaGetSymbolAddress((void**)&pattn, g_attn);
    cudaGetSymbolAddress((void**)&ph1,   g_h1);
    cudaGetSymbolAddress((void**)&pffn,  g_ffn);
    cudaGetSymbolAddress((void**)&pxr,   g_xr);
    cudaGetSymbolAddress((void**)&pwr,   g_wr);
    cudaGetSymbolAddress((void**)&pbias, g_bqkv);
    cudaGetSymbolAddress((void**)&prsum, g_rowsum);
    cudaGetSymbolAddress((void**)&prinv, g_rowinv);

    float* rWqkv = pwr;                    // 3M floats: Wq|Wk|Wv
    float* rWf   = pwr + 3*1024*1024;
    float* rW1   = pwr + 4*1024*1024;
    float* rW2   = pwr + 6*1024*1024;

    cudaFuncSetAttribute(gemm_mma<128,0>, cudaFuncAttributeMaxDynamicSharedMemorySize, SMEM_GEMM);
    cudaFuncSetAttribute(gemm_mma<128,1>, cudaFuncAttributeMaxDynamicSharedMemorySize, SMEM_GEMM);
    cudaFuncSetAttribute(gemm_mma<64,2>,  cudaFuncAttributeMaxDynamicSharedMemorySize, SMEM_PV);

    const float isq = 0.125f;  // 1/sqrt(64)

    // ---- prep: one batched rounding pass, bias concat, rowsum zero ----
    RC7 rc;
    rc.in[0] = x;  rc.out[0] = pxr;                 rc.n4[0] = MTOK*DIM/4;
    rc.in[1] = Wq; rc.out[1] = rWqkv;               rc.n4[1] = DIM*DIM/4;
    rc.in[2] = Wk; rc.out[2] = rWqkv + 1024*1024;   rc.n4[2] = DIM*DIM/4;
    rc.in[3] = Wv; rc.out[3] = rWqkv + 2*1024*1024; rc.n4[3] = DIM*DIM/4;
    rc.in[4] = Wf; rc.out[4] = rWf;                 rc.n4[4] = DIM*DIM/4;
    rc.in[5] = W1; rc.out[5] = rW1;                 rc.n4[5] = FFD*DIM/4;
    rc.in[6] = W2; rc.out[6] = rW2;                 rc.n4[6] = FFD*DIM/4;
    round_multi<<<dim3(512, 7), 256>>>(rc);
    concat_bias<<<12, 256>>>(bq, bk, bv, pbias);
    zero_buf<<<NROW/256, 256>>>(prsum, NROW);

    // ---- fused QKV projection (q cols scaled by 1/sqrt(dh); all rounded) ----
    gemm_mma<128,0><<<dim3(QKVD/128, MTOK/128), 256, SMEM_GEMM>>>(
        pxr, rWqkv, pbias, nullptr, pqkv, DIM, DIM, DIM, QKVD,
        isq, DIM, 0, 1, nullptr, nullptr);

    // ---- scores: e = exp(q.k^T) -> score region; rowsums accumulated ----
    gemm_mma<128,1><<<dim3(SEQ/128, SEQ/128, BSZ*NH), 256, SMEM_GEMM>>>(
        pqkv, pqkv + DIM, nullptr, nullptr, score, DH, QKVD, QKVD, SEQ,
        1.f, 0, 0, 0, prsum, nullptr);
    recip_buf<<<NROW/256, 256>>>(prsum, prinv, NROW);

    // ---- PV: fragments normalized on the fly; fp32 P written to d_out ----
    gemm_mma<64,2><<<dim3(1, SEQ/128, BSZ*NH), 256, SMEM_PV>>>(
        score, pqkv + 2*DIM, nullptr, nullptr, pattn, SEQ, SEQ, QKVD, DIM,
        1.f, 0, 0, 1, nullptr, prinv);

    // ---- output projection + residual, LN1 ----
    gemm_mma<128,0><<<dim3(DIM/128, MTOK/128), 256, SMEM_GEMM>>>(
        pattn, rWf, bf, x, ph1, DIM, DIM, DIM, DIM,
        1.f, 0, 0, 0, nullptr, nullptr);
    layernorm_row<<<MTOK, 256>>>(ph1, ph1, g1, be1, 1);

    // ---- FFN ----
    gemm_mma<128,0><<<dim3(FFD/128, MTOK/128), 256, SMEM_GEMM>>>(
        ph1, rW1, b1, nullptr, pffn, DIM, DIM, DIM, FFD,
        1.f, 0, 1, 1, nullptr, nullptr);
    gemm_mma<128,0><<<dim3(DIM/128, MTOK/128), 256, SMEM_GEMM>>>(
        pffn, rW2, b2, ph1, pxr, FFD, FFD, FFD, DIM,
        1.f, 0, 0, 0, nullptr, nullptr);
    layernorm_row<<<MTOK, 256>>>(pxr, out, g2, be2, 0);
}